// round 11
// baseline (speedup 1.0000x reference)
#include <cuda_runtime.h>
#include <cuda_bf16.h>
#include <math.h>

typedef unsigned int u32;
typedef unsigned long long u64;

#define H      1900
#define NB     256
#define BB     512
#define TST    153
#define TEPI   25
#define PADTOK 26
#define LDK    3840      // extended K stride: hi(1920) | lo(1920)
#define NP1    1920
#define NP2    7680
#define CH1    90        // GEMM1 chunks: 3 passes x 30 chunks of K=64
#define CH2    91        // GEMM2: + 1 x-ext chunk

// ---------------- device scratch ----------------
__device__ __align__(16) __nv_bfloat16 g_whT [(size_t)NP2 * LDK]; // gate-interleaved [p=4j+g][k hi|lo]
__device__ __align__(16) __nv_bfloat16 g_wmhT[(size_t)NP1 * LDK];
__device__ __align__(16) __nv_bfloat16 g_hext[(size_t)BB * LDK];
__device__ __align__(16) __nv_bfloat16 g_mext[(size_t)BB * LDK];
__device__ __align__(16) __nv_bfloat16 g_xext[(size_t)TST * BB * 64]; // per-step x packet
__device__ __align__(16) __nv_bfloat16 g_wxext[(size_t)NP2 * 64];    // wx/bias packet (interleaved cols)
__device__ __align__(16) float g_c[BB * NP1];
__device__ __align__(16) float g_wmxp[10 * NP1];
__device__ __align__(16) float g_xs[(size_t)TST * BB * 10];
__device__ __align__(16) float g_toth[NB * H];
__device__ __align__(16) float g_epih[NB * H];
__device__ int g_ei[NB];
__device__ int g_ti[NB];

// ---------------- helpers ----------------
__device__ __forceinline__ u32 smem_u32(const void* p) {
    u32 a;
    asm("{ .reg .u64 t; cvta.to.shared.u64 t, %1; cvt.u32.u64 %0, t; }" : "=r"(a) : "l"(p));
    return a;
}
#define SWZ128(o) ((u32)(o) ^ ((((u32)(o)) >> 3) & 0x70u))
__device__ __forceinline__ void cp16(u32 dst, const void* src) {
    asm volatile("cp.async.cg.shared.global [%0], [%1], 16;" :: "r"(dst), "l"(src) : "memory");
}
__device__ __forceinline__ float sigmf(float x) { return 1.f / (1.f + expf(-x)); }

// ---------------- prep kernels ----------------
__global__ void wnormT_kernel(const float* __restrict__ w, const float* __restrict__ g, int mode)
{
    // mode 0: wh [1900,7600] -> g_whT gate-interleaved ; mode 1: wmh [1900,1900] -> g_wmhT
    int p = blockIdx.x * blockDim.x + threadIdx.x;
    const int NP = mode ? NP1 : NP2;
    if (p >= NP) return;
    __nv_bfloat16* out = (mode ? g_wmhT : g_whT) + (size_t)p * LDK;
    int n; bool valid;
    if (mode) { n = p; valid = (p < 1900); }
    else      { int j = p >> 2, gg = p & 3; n = gg * 1900 + j; valid = (j < 1900); }
    const int N = mode ? 1900 : 7600;
    if (!valid) { u32* o = (u32*)out; for (int i = 0; i < LDK / 2; i++) o[i] = 0u; return; }
    float s = 0.f;
    for (int k = 0; k < 1900; k++) { float v = w[(size_t)k * N + n]; s += v * v; }
    float sc = g[n] * rsqrtf(fmaxf(s, 1e-12f));
    for (int k0 = 0; k0 < NP1; k0 += 8) {
        union { __nv_bfloat16 b[8]; uint4 v; } Hi, Lo;
#pragma unroll
        for (int e = 0; e < 8; e++) {
            int k = k0 + e;
            float v = (k < 1900) ? w[(size_t)k * N + n] * sc : 0.f;
            __nv_bfloat16 hb = __float2bfloat16(v);
            Hi.b[e] = hb;
            Lo.b[e] = __float2bfloat16(v - __bfloat162float(hb));
        }
        *(uint4*)(out + k0)       = Hi.v;
        *(uint4*)(out + NP1 + k0) = Lo.v;
    }
}

__global__ void wmx_kernel(const float* __restrict__ w, const float* __restrict__ g)
{
    int n = blockIdx.x * blockDim.x + threadIdx.x;
    if (n >= NP1) return;
    if (n >= 1900) { for (int k = 0; k < 10; k++) g_wmxp[k * NP1 + n] = 0.f; return; }
    float s = 0.f;
    for (int k = 0; k < 10; k++) { float v = w[k * 1900 + n]; s += v * v; }
    float sc = g[n] * rsqrtf(fmaxf(s, 1e-12f));
    for (int k = 0; k < 10; k++) g_wmxp[k * NP1 + n] = w[k * 1900 + n] * sc;
}

__global__ void wxext_kernel(const float* __restrict__ wx, const float* __restrict__ gx,
                             const float* __restrict__ b)
{
    // g_wxext[p][0..9]=wx_hi  [10..19]=wx_hi  [20..29]=wx_lo  [30]=b_hi [31]=b_lo  rest 0
    int p = blockIdx.x * blockDim.x + threadIdx.x;
    if (p >= NP2) return;
    __nv_bfloat16* out = g_wxext + (size_t)p * 64;
    int j = p >> 2, gg = p & 3, n = gg * 1900 + j;
    for (int k = 0; k < 64; k++) out[k] = __float2bfloat16(0.f);
    if (j >= 1900) return;
    float s = 0.f;
    for (int k = 0; k < 10; k++) { float v = wx[k * 7600 + n]; s += v * v; }
    float sc = gx[n] * rsqrtf(fmaxf(s, 1e-12f));
    for (int e = 0; e < 10; e++) {
        float v = wx[e * 7600 + n] * sc;
        __nv_bfloat16 hb = __float2bfloat16(v);
        out[e] = hb;
        out[10 + e] = hb;
        out[20 + e] = __float2bfloat16(v - __bfloat162float(hb));
    }
    float bv = b[n];
    __nv_bfloat16 bh = __float2bfloat16(bv);
    out[30] = bh;
    out[31] = __float2bfloat16(bv - __bfloat162float(bh));
}

__global__ void lengths_kernel(const int* __restrict__ epi, const int* __restrict__ lft,
                               const int* __restrict__ rgt)
{
    int b = blockIdx.x * blockDim.x + threadIdx.x;
    if (b >= NB) return;
    int el = 0; for (int t = 0; t < TEPI; t++) el += (epi[b * TEPI + t] != PADTOK);
    int ll = 0; for (int t = 0; t < 64;   t++) ll += (lft[b * 64 + t]   != PADTOK);
    int rl = 0; for (int t = 0; t < 64;   t++) rl += (rgt[b * 64 + t]   != PADTOK);
    ll = max(ll, 1); rl = max(rl, 1);
    int tl = el + ll + rl;
    g_ei[b] = min(max(el - 1, 0), TEPI - 1);
    g_ti[b] = min(max(tl - 1, 0), TST - 1);
}

__global__ void embed_kernel(const int* __restrict__ epi, const int* __restrict__ tot,
                             const float* __restrict__ embed)
{
    int idx = blockIdx.x * blockDim.x + threadIdx.x;
    if (idx >= TST * BB) return;
    int t = idx / BB, row = idx % BB;
    int tok;
    if (row < NB) tok = tot[row * TST + t];
    else { if (t >= TEPI) return; tok = epi[(row - NB) * TEPI + t]; }
    float x[10];
    for (int e = 0; e < 10; e++) x[e] = embed[tok * 10 + e];
    float* xs = &g_xs[(size_t)idx * 10];
    for (int e = 0; e < 10; e++) xs[e] = x[e];
    __nv_bfloat16* xe = &g_xext[(size_t)idx * 64];
    for (int k = 0; k < 64; k++) xe[k] = __float2bfloat16(0.f);
    for (int e = 0; e < 10; e++) {
        __nv_bfloat16 hb = __float2bfloat16(x[e]);
        xe[e] = hb;
        xe[10 + e] = __float2bfloat16(x[e] - __bfloat162float(hb));
        xe[20 + e] = hb;
    }
    xe[30] = __float2bfloat16(1.f);
    xe[31] = __float2bfloat16(1.f);
}

__global__ void init_kernel()
{
    int i = blockIdx.x * blockDim.x + threadIdx.x;
    if (i < BB * NP1) { ((u32*)g_hext)[i] = 0u; ((u32*)g_mext)[i] = 0u; g_c[i] = 0.f; }
}

// ---------------- GEMM1: m = (x@wmx) .* (h@wmh) ; 256 thr, tile 64x64, 3 stages ----------------
__global__ void __launch_bounds__(256) gemm1(int t)
{
    constexpr int TM = 64, TN = 64, STG = (TM + TN) * 128;
    extern __shared__ char smraw[];
    char* tiles = (char*)((((u64)smraw) + 1023) & ~(u64)1023);
    const u32 tb0 = smem_u32(tiles);
    const int tid = threadIdx.x, lane = tid & 31, wid = tid >> 5;
    const int wm0 = (wid >> 2) * 32, wn0 = (wid & 3) * 16;
    const int row0 = blockIdx.y * TM, col0 = blockIdx.x * TN;

    float d[2][2][4] = {};

    auto load_chunk = [&](int c, int s) {
        int p = c / 30, kc = c - p * 30;
        int ak = ((p == 1) ? NP1 : 0) + kc * 64;
        int bk = ((p == 2) ? NP1 : 0) + kc * 64;
        u32 tb = tb0 + s * STG;
#pragma unroll
        for (int i = 0; i < 2; i++) {
            int seg = tid + i * 256; int r = seg >> 3; int o = (seg & 7) * 16;
            cp16(tb + SWZ128(r * 128 + o),
                 (const char*)(g_hext + (size_t)(row0 + r) * LDK + ak) + o);
        }
#pragma unroll
        for (int i = 0; i < 2; i++) {
            int seg = tid + i * 256; int r = seg >> 3; int o = (seg & 7) * 16;
            cp16(tb + TM * 128 + SWZ128(r * 128 + o),
                 (const char*)(g_wmhT + (size_t)(col0 + r) * LDK + bk) + o);
        }
        asm volatile("cp.async.commit_group;" ::: "memory");
    };

    load_chunk(0, 0); load_chunk(1, 1); load_chunk(2, 2);

    for (int c = 0; c < CH1; c++) {
        int s = c % 3;
        int pend = CH1 - 1 - c;
        if (pend >= 2)      asm volatile("cp.async.wait_group 2;" ::: "memory");
        else if (pend == 1) asm volatile("cp.async.wait_group 1;" ::: "memory");
        else                asm volatile("cp.async.wait_group 0;" ::: "memory");
        __syncthreads();
        const u32 As = tb0 + s * STG, Bs = As + TM * 128;
#pragma unroll
        for (int k16 = 0; k16 < 4; k16++) {
            u32 a[2][4], b[2][2];
#pragma unroll
            for (int mi = 0; mi < 2; mi++) {
                int r = wm0 + mi * 16 + (lane & 15);
                int cb = k16 * 32 + (lane >> 4) * 16;
                u32 ad = As + r * 128 + (cb ^ ((r & 7) << 4));
                asm volatile("ldmatrix.sync.aligned.m8n8.x4.shared.b16 {%0,%1,%2,%3}, [%4];"
                    : "=r"(a[mi][0]), "=r"(a[mi][1]), "=r"(a[mi][2]), "=r"(a[mi][3]) : "r"(ad));
            }
            {
                int l = lane & 7, q = lane >> 3;
                int r = wn0 + (q >> 1) * 8 + l;
                int cb = k16 * 32 + (q & 1) * 16;
                u32 ad = Bs + r * 128 + (cb ^ ((r & 7) << 4));
                asm volatile("ldmatrix.sync.aligned.m8n8.x4.shared.b16 {%0,%1,%2,%3}, [%4];"
                    : "=r"(b[0][0]), "=r"(b[0][1]), "=r"(b[1][0]), "=r"(b[1][1]) : "r"(ad));
            }
#pragma unroll
            for (int mi = 0; mi < 2; mi++)
#pragma unroll
                for (int ni = 0; ni < 2; ni++)
                    asm volatile("mma.sync.aligned.m16n8k16.row.col.f32.bf16.bf16.f32 "
                        "{%0,%1,%2,%3}, {%4,%5,%6,%7}, {%8,%9}, {%0,%1,%2,%3};"
                        : "+f"(d[mi][ni][0]), "+f"(d[mi][ni][1]),
                          "+f"(d[mi][ni][2]), "+f"(d[mi][ni][3])
                        : "r"(a[mi][0]), "r"(a[mi][1]), "r"(a[mi][2]), "r"(a[mi][3]),
                          "r"(b[ni][0]), "r"(b[ni][1]));
        }
        __syncthreads();
        if (c + 3 < CH1) load_chunk(c + 3, s);
    }

    // epilogue: m = (x@wmx) .* acc
    __syncthreads();
    float* xsh = (float*)tiles;          // [TM][10]
    float* wsh = xsh + TM * 10;          // [10][TN]
    for (int i = tid; i < TM * 10; i += 256)
        xsh[i] = g_xs[((size_t)t * BB + row0 + i / 10) * 10 + (i % 10)];
    for (int i = tid; i < 10 * TN; i += 256)
        wsh[i] = g_wmxp[(i / TN) * NP1 + col0 + (i % TN)];
    __syncthreads();

#pragma unroll
    for (int mi = 0; mi < 2; mi++)
#pragma unroll
        for (int rh = 0; rh < 2; rh++) {
            int rl = wm0 + mi * 16 + (lane >> 2) + rh * 8;
            int r = row0 + rl;
            float xv[10];
#pragma unroll
            for (int e = 0; e < 10; e++) xv[e] = xsh[rl * 10 + e];
#pragma unroll
            for (int ni = 0; ni < 2; ni++)
#pragma unroll
                for (int c2 = 0; c2 < 2; c2++) {
                    int nl = wn0 + ni * 8 + (lane & 3) * 2 + c2;
                    int n = col0 + nl;
                    if (n < H) {
                        float xp = 0.f;
#pragma unroll
                        for (int e = 0; e < 10; e++) xp += xv[e] * wsh[e * TN + nl];
                        float mv = xp * d[mi][ni][rh * 2 + c2];
                        __nv_bfloat16 hb = __float2bfloat16(mv);
                        g_mext[(size_t)r * LDK + n] = hb;
                        g_mext[(size_t)r * LDK + NP1 + n] =
                            __float2bfloat16(mv - __bfloat162float(hb));
                    }
                }
        }
}

// ---------------- GEMM2 + gates: 512 thr, tile 128x128, 3 stages, x folded into K ----------------
__global__ void __launch_bounds__(512) gemm2(int t)
{
    constexpr int TM = 128, TN = 128, STG = (TM + TN) * 128;
    extern __shared__ char smraw[];
    char* tiles = (char*)((((u64)smraw) + 1023) & ~(u64)1023);
    const u32 tb0 = smem_u32(tiles);
    const int tid = threadIdx.x, lane = tid & 31, wid = tid >> 5;
    const int wm0 = (wid >> 2) * 32, wn0 = (wid & 3) * 32;
    const int row0 = blockIdx.y * TM, col0 = blockIdx.x * TN;

    float d[2][4][4] = {};

    auto load_chunk = [&](int c, int s) {
        u32 tb = tb0 + s * STG;
        const char *abase, *bbase; size_t astr, bstr;
        if (c < 90) {
            int p = c / 30, kc = c - p * 30;
            int ak = ((p == 1) ? NP1 : 0) + kc * 64;
            int bk = ((p == 2) ? NP1 : 0) + kc * 64;
            abase = (const char*)(g_mext + (size_t)row0 * LDK + ak); astr = LDK * 2;
            bbase = (const char*)(g_whT + (size_t)col0 * LDK + bk);  bstr = LDK * 2;
        } else {
            abase = (const char*)(g_xext + ((size_t)t * BB + row0) * 64); astr = 128;
            bbase = (const char*)(g_wxext + (size_t)col0 * 64);           bstr = 128;
        }
#pragma unroll
        for (int i = 0; i < 2; i++) {
            int seg = tid + i * 512; int r = seg >> 3; int o = (seg & 7) * 16;
            cp16(tb + SWZ128(r * 128 + o), abase + (size_t)r * astr + o);
        }
#pragma unroll
        for (int i = 0; i < 2; i++) {
            int seg = tid + i * 512; int r = seg >> 3; int o = (seg & 7) * 16;
            cp16(tb + TM * 128 + SWZ128(r * 128 + o), bbase + (size_t)r * bstr + o);
        }
        asm volatile("cp.async.commit_group;" ::: "memory");
    };

    load_chunk(0, 0); load_chunk(1, 1); load_chunk(2, 2);

    for (int c = 0; c < CH2; c++) {
        int s = c % 3;
        int pend = CH2 - 1 - c;
        if (pend >= 2)      asm volatile("cp.async.wait_group 2;" ::: "memory");
        else if (pend == 1) asm volatile("cp.async.wait_group 1;" ::: "memory");
        else                asm volatile("cp.async.wait_group 0;" ::: "memory");
        __syncthreads();
        const u32 As = tb0 + s * STG, Bs = As + TM * 128;
#pragma unroll
        for (int k16 = 0; k16 < 4; k16++) {
            u32 a[2][4], b[4][2];
#pragma unroll
            for (int mi = 0; mi < 2; mi++) {
                int r = wm0 + mi * 16 + (lane & 15);
                int cb = k16 * 32 + (lane >> 4) * 16;
                u32 ad = As + r * 128 + (cb ^ ((r & 7) << 4));
                asm volatile("ldmatrix.sync.aligned.m8n8.x4.shared.b16 {%0,%1,%2,%3}, [%4];"
                    : "=r"(a[mi][0]), "=r"(a[mi][1]), "=r"(a[mi][2]), "=r"(a[mi][3]) : "r"(ad));
            }
#pragma unroll
            for (int nb = 0; nb < 2; nb++) {
                int l = lane & 7, q = lane >> 3;
                int r = wn0 + nb * 16 + (q >> 1) * 8 + l;
                int cb = k16 * 32 + (q & 1) * 16;
                u32 ad = Bs + r * 128 + (cb ^ ((r & 7) << 4));
                asm volatile("ldmatrix.sync.aligned.m8n8.x4.shared.b16 {%0,%1,%2,%3}, [%4];"
                    : "=r"(b[nb*2][0]), "=r"(b[nb*2][1]), "=r"(b[nb*2+1][0]), "=r"(b[nb*2+1][1]) : "r"(ad));
            }
#pragma unroll
            for (int mi = 0; mi < 2; mi++)
#pragma unroll
                for (int ni = 0; ni < 4; ni++)
                    asm volatile("mma.sync.aligned.m16n8k16.row.col.f32.bf16.bf16.f32 "
                        "{%0,%1,%2,%3}, {%4,%5,%6,%7}, {%8,%9}, {%0,%1,%2,%3};"
                        : "+f"(d[mi][ni][0]), "+f"(d[mi][ni][1]),
                          "+f"(d[mi][ni][2]), "+f"(d[mi][ni][3])
                        : "r"(a[mi][0]), "r"(a[mi][1]), "r"(a[mi][2]), "r"(a[mi][3]),
                          "r"(b[ni][0]), "r"(b[ni][1]));
        }
        __syncthreads();
        if (c + 3 < CH2) load_chunk(c + 3, s);
    }

    // ---- epilogue: exchange accs via smem, then full LSTM gate math ----
    __syncthreads();
    float* zt = (float*)tiles;   // [128][128] f32 = 64KB (stage region reuse)
#pragma unroll
    for (int mi = 0; mi < 2; mi++)
#pragma unroll
        for (int rh = 0; rh < 2; rh++) {
            int r = wm0 + mi * 16 + (lane >> 2) + rh * 8;
#pragma unroll
            for (int ni = 0; ni < 4; ni++) {
                int col = wn0 + ni * 8 + (lane & 3) * 2;
                *(float2*)&zt[r * 128 + col] =
                    make_float2(d[mi][ni][rh * 2], d[mi][ni][rh * 2 + 1]);
            }
        }
    __syncthreads();

    const int u = tid & 31, rgrp = tid >> 5;
    const int j = blockIdx.x * 32 + u;        // hidden unit (interleave: cols 4j+g)
    const bool jv = (j < H);
#pragma unroll
    for (int k = 0; k < 8; k++) {
        int r = rgrp + 16 * k;
        float4 q = *(float4*)&zt[r * 128 + u * 4];   // i, f, o, u
        if (jv) {
            int row = row0 + r;
            float c = g_c[row * NP1 + j];
            c = sigmf(q.y) * c + sigmf(q.x) * tanhf(q.w);
            float h = sigmf(q.z) * tanhf(c);
            g_c[row * NP1 + j] = c;
            __nv_bfloat16 hb = __float2bfloat16(h);
            g_hext[(size_t)row * LDK + j] = hb;
            g_hext[(size_t)row * LDK + NP1 + j] = __float2bfloat16(h - __bfloat162float(hb));
            if (row < NB) { if (g_ti[row] == t) g_toth[row * H + j] = h; }
            else { int b2 = row - NB; if (g_ei[b2] == t) g_epih[b2 * H + j] = h; }
        }
    }
}

// ---------------- classifier ----------------
__global__ void classifier_kernel(
    const float* __restrict__ bn1g, const float* __restrict__ bn1b,
    const float* __restrict__ bn1m, const float* __restrict__ bn1v,
    const float* __restrict__ W1,  const float* __restrict__ b1,
    const float* __restrict__ bn2g, const float* __restrict__ bn2b,
    const float* __restrict__ bn2m, const float* __restrict__ bn2v,
    const float* __restrict__ W2,  const float* __restrict__ b2,
    float* __restrict__ out)
{
    __shared__ float xsh[2 * H];
    __shared__ float ysh[380];
    __shared__ float red[256];
    const int b = blockIdx.x, tid = threadIdx.x;
    const int IC = 2 * H, OC = 380;
    for (int k = tid; k < IC; k += 256) {
        float v = (k < H) ? g_toth[b * H + k] : g_epih[b * H + (k - H)];
        v = (v >= 0.f) ? v : 0.3f * v;
        v = (v - bn1m[k]) / sqrtf(bn1v[k] + 1e-3f) * bn1g[k] + bn1b[k];
        xsh[k] = v;
    }
    __syncthreads();
    for (int col = tid; col < OC; col += 256) {
        float s = b1[col];
        for (int k = 0; k < IC; k++) s += xsh[k] * W1[k * OC + col];
        s = (s >= 0.f) ? s : 0.3f * s;
        s = (s - bn2m[col]) / sqrtf(bn2v[col] + 1e-3f) * bn2g[col] + bn2b[col];
        ysh[col] = s;
    }
    __syncthreads();
    float acc = 0.f;
    for (int k = tid; k < OC; k += 256) acc += ysh[k] * W2[k];
    red[tid] = acc;
    __syncthreads();
    for (int s = 128; s > 0; s >>= 1) { if (tid < s) red[tid] += red[tid + s]; __syncthreads(); }
    if (tid == 0) out[b] = red[0] + b2[0];
}

// ---------------- launch ----------------
extern "C" void kernel_launch(void* const* d_in, const int* in_sizes, int n_in,
                              void* d_out, int out_size)
{
    const int*   epi   = (const int*)  d_in[0];
    const int*   lft   = (const int*)  d_in[1];
    const int*   rgt   = (const int*)  d_in[2];
    const int*   tot   = (const int*)  d_in[3];
    const float* embed = (const float*)d_in[4];
    const float* wx    = (const float*)d_in[5];
    const float* wh    = (const float*)d_in[6];
    const float* wmx   = (const float*)d_in[7];
    const float* wmh   = (const float*)d_in[8];
    const float* bb    = (const float*)d_in[9];
    const float* gx    = (const float*)d_in[10];
    const float* gh    = (const float*)d_in[11];
    const float* gmx   = (const float*)d_in[12];
    const float* gmh   = (const float*)d_in[13];
    float* out = (float*)d_out;

    const int SM1 = 1024 + 3 * (64 + 64) * 128;     // ~49 KB
    const int SM2 = 1024 + 3 * (128 + 128) * 128;   // ~97 KB
    cudaFuncSetAttribute(gemm1, cudaFuncAttributeMaxDynamicSharedMemorySize, SM1);
    cudaFuncSetAttribute(gemm2, cudaFuncAttributeMaxDynamicSharedMemorySize, SM2);

    wnormT_kernel<<<(NP2 + 63) / 64, 64>>>(wh, gh, 0);
    wnormT_kernel<<<(NP1 + 63) / 64, 64>>>(wmh, gmh, 1);
    wmx_kernel<<<(NP1 + 127) / 128, 128>>>(wmx, gmx);
    wxext_kernel<<<(NP2 + 127) / 128, 128>>>(wx, gx, bb);
    lengths_kernel<<<1, 256>>>(epi, lft, rgt);
    embed_kernel<<<(TST * BB + 255) / 256, 256>>>(epi, tot, embed);
    init_kernel<<<(BB * NP1 + 255) / 256, 256>>>();

    for (int t = 0; t < TST; t++) {
        const int Mt = (t < TEPI) ? BB : NB;
        gemm1<<<dim3(NP1 / 64, Mt / 64), 256, SM1>>>(t);
        gemm2<<<dim3(NP2 / 128, Mt / 128), 512, SM2>>>(t);
    }

    classifier_kernel<<<NB, 256>>>(
        (const float*)d_in[14], (const float*)d_in[15], (const float*)d_in[16], (const float*)d_in[17],
        (const float*)d_in[18], (const float*)d_in[19],
        (const float*)d_in[20], (const float*)d_in[21], (const float*)d_in[22], (const float*)d_in[23],
        (const float*)d_in[24], (const float*)d_in[25], out);
}

// round 14
// speedup vs baseline: 1.4906x; 1.4906x over previous
#include <cuda_runtime.h>
#include <cuda_fp16.h>
#include <math.h>

typedef unsigned int u32;
typedef unsigned long long u64;

#define H      1900
#define NB     256
#define BB     512
#define TST    153
#define TEPI   25
#define PADTOK 26
#define LDA    3840      // activation K stride: hi(1920) | lo(1920)
#define LDW    1920      // weight K stride (single fp16 plane)
#define NP1    1920
#define NP2    7680
#define CH1    60        // GEMM1 chunks: 2 passes x 30 chunks of K=64
#define CH2    61        // GEMM2: + 1 x-ext chunk

// ---------------- device scratch ----------------
__device__ __align__(16) __half g_whT [(size_t)NP2 * LDW]; // gate-interleaved [p=4j+g][k]
__device__ __align__(16) __half g_wmhT[(size_t)NP1 * LDW];
__device__ __align__(16) __half g_hext[(size_t)BB * LDA];
__device__ __align__(16) __half g_mext[(size_t)BB * LDA];
__device__ __align__(16) __half g_xext[(size_t)TST * BB * 64]; // per-step x packet
__device__ __align__(16) __half g_wxext[(size_t)NP2 * 64];    // wx/bias packet (interleaved cols)
__device__ __align__(16) float g_c[BB * NP1];
__device__ __align__(16) float g_wmxp[10 * NP1];
__device__ __align__(16) float g_xs[(size_t)TST * BB * 10];
__device__ __align__(16) float g_toth[NB * H];
__device__ __align__(16) float g_epih[NB * H];
__device__ int g_ei[NB];
__device__ int g_ti[NB];

// ---------------- helpers ----------------
__device__ __forceinline__ u32 smem_u32(const void* p) {
    u32 a;
    asm("{ .reg .u64 t; cvta.to.shared.u64 t, %1; cvt.u32.u64 %0, t; }" : "=r"(a) : "l"(p));
    return a;
}
#define SWZ128(o) ((u32)(o) ^ ((((u32)(o)) >> 3) & 0x70u))
__device__ __forceinline__ void cp16(u32 dst, const void* src) {
    asm volatile("cp.async.cg.shared.global [%0], [%1], 16;" :: "r"(dst), "l"(src) : "memory");
}
__device__ __forceinline__ float sigmf(float x) { return 1.f / (1.f + expf(-x)); }

// ---------------- prep kernels ----------------
__global__ void wnormT_kernel(const float* __restrict__ w, const float* __restrict__ g, int mode)
{
    // mode 0: wh [1900,7600] -> g_whT gate-interleaved ; mode 1: wmh [1900,1900] -> g_wmhT
    int p = blockIdx.x * blockDim.x + threadIdx.x;
    const int NP = mode ? NP1 : NP2;
    if (p >= NP) return;
    __half* out = (mode ? g_wmhT : g_whT) + (size_t)p * LDW;
    int n; bool valid;
    if (mode) { n = p; valid = (p < 1900); }
    else      { int j = p >> 2, gg = p & 3; n = gg * 1900 + j; valid = (j < 1900); }
    const int N = mode ? 1900 : 7600;
    if (!valid) { u32* o = (u32*)out; for (int i = 0; i < LDW / 2; i++) o[i] = 0u; return; }
    float s = 0.f;
    for (int k = 0; k < 1900; k++) { float v = w[(size_t)k * N + n]; s += v * v; }
    float sc = g[n] * rsqrtf(fmaxf(s, 1e-12f));
    for (int k0 = 0; k0 < LDW; k0 += 8) {
        union { __half b[8]; uint4 v; } Hi;
#pragma unroll
        for (int e = 0; e < 8; e++) {
            int k = k0 + e;
            float v = (k < 1900) ? w[(size_t)k * N + n] * sc : 0.f;
            Hi.b[e] = __float2half(v);
        }
        *(uint4*)(out + k0) = Hi.v;
    }
}

__global__ void wmx_kernel(const float* __restrict__ w, const float* __restrict__ g)
{
    int n = blockIdx.x * blockDim.x + threadIdx.x;
    if (n >= NP1) return;
    if (n >= 1900) { for (int k = 0; k < 10; k++) g_wmxp[k * NP1 + n] = 0.f; return; }
    float s = 0.f;
    for (int k = 0; k < 10; k++) { float v = w[k * 1900 + n]; s += v * v; }
    float sc = g[n] * rsqrtf(fmaxf(s, 1e-12f));
    for (int k = 0; k < 10; k++) g_wmxp[k * NP1 + n] = w[k * 1900 + n] * sc;
}

__global__ void wxext_kernel(const float* __restrict__ wx, const float* __restrict__ gx,
                             const float* __restrict__ b)
{
    // g_wxext[p][0..9]=wx  [10..19]=wx  [20]=b_hi [21]=b_lo  rest 0
    int p = blockIdx.x * blockDim.x + threadIdx.x;
    if (p >= NP2) return;
    __half* out = g_wxext + (size_t)p * 64;
    int j = p >> 2, gg = p & 3, n = gg * 1900 + j;
    for (int k = 0; k < 64; k++) out[k] = __float2half(0.f);
    if (j >= 1900) return;
    float s = 0.f;
    for (int k = 0; k < 10; k++) { float v = wx[k * 7600 + n]; s += v * v; }
    float sc = gx[n] * rsqrtf(fmaxf(s, 1e-12f));
    for (int e = 0; e < 10; e++) {
        float v = wx[e * 7600 + n] * sc;
        __half hb = __float2half(v);
        out[e] = hb;
        out[10 + e] = hb;
    }
    float bv = b[n];
    __half bh = __float2half(bv);
    out[20] = bh;
    out[21] = __float2half(bv - __half2float(bh));
}

__global__ void lengths_kernel(const int* __restrict__ epi, const int* __restrict__ lft,
                               const int* __restrict__ rgt)
{
    int b = blockIdx.x * blockDim.x + threadIdx.x;
    if (b >= NB) return;
    int el = 0; for (int t = 0; t < TEPI; t++) el += (epi[b * TEPI + t] != PADTOK);
    int ll = 0; for (int t = 0; t < 64;   t++) ll += (lft[b * 64 + t]   != PADTOK);
    int rl = 0; for (int t = 0; t < 64;   t++) rl += (rgt[b * 64 + t]   != PADTOK);
    ll = max(ll, 1); rl = max(rl, 1);
    int tl = el + ll + rl;
    g_ei[b] = min(max(el - 1, 0), TEPI - 1);
    g_ti[b] = min(max(tl - 1, 0), TST - 1);
}

__global__ void embed_kernel(const int* __restrict__ epi, const int* __restrict__ tot,
                             const float* __restrict__ embed)
{
    int idx = blockIdx.x * blockDim.x + threadIdx.x;
    if (idx >= TST * BB) return;
    int t = idx / BB, row = idx % BB;
    int tok;
    if (row < NB) tok = tot[row * TST + t];
    else { if (t >= TEPI) return; tok = epi[(row - NB) * TEPI + t]; }
    float x[10];
    for (int e = 0; e < 10; e++) x[e] = embed[tok * 10 + e];
    float* xs = &g_xs[(size_t)idx * 10];
    for (int e = 0; e < 10; e++) xs[e] = x[e];
    __half* xe = &g_xext[(size_t)idx * 64];
    for (int k = 0; k < 64; k++) xe[k] = __float2half(0.f);
    for (int e = 0; e < 10; e++) {
        __half hb = __float2half(x[e]);
        xe[e] = hb;
        xe[10 + e] = __float2half(x[e] - __half2float(hb));
    }
    xe[20] = __float2half(1.f);
    xe[21] = __float2half(1.f);
}

__global__ void init_kernel()
{
    int i = blockIdx.x * blockDim.x + threadIdx.x;
    if (i < BB * NP1) { ((u32*)g_hext)[i] = 0u; ((u32*)g_mext)[i] = 0u; g_c[i] = 0.f; }
}

// ---------------- GEMM1: m = (x@wmx) .* (h@wmh) ; 256 thr, tile 64x64, 3 stages ----------------
__global__ void __launch_bounds__(256) gemm1(int t)
{
    constexpr int TM = 64, TN = 64, STG = (TM + TN) * 128;
    extern __shared__ char smraw[];
    char* tiles = (char*)((((u64)smraw) + 1023) & ~(u64)1023);
    const u32 tb0 = smem_u32(tiles);
    const int tid = threadIdx.x, lane = tid & 31, wid = tid >> 5;
    const int wm0 = (wid >> 2) * 32, wn0 = (wid & 3) * 16;
    const int row0 = blockIdx.y * TM, col0 = blockIdx.x * TN;

    float d[2][2][4] = {};

    auto load_chunk = [&](int c, int s) {
        int p = c / 30, kc = c - p * 30;
        int ak = p * 1920 + kc * 64;
        int bk = kc * 64;
        u32 tb = tb0 + s * STG;
#pragma unroll
        for (int i = 0; i < 2; i++) {
            int seg = tid + i * 256; int r = seg >> 3; int o = (seg & 7) * 16;
            cp16(tb + SWZ128(r * 128 + o),
                 (const char*)(g_hext + (size_t)(row0 + r) * LDA + ak) + o);
        }
#pragma unroll
        for (int i = 0; i < 2; i++) {
            int seg = tid + i * 256; int r = seg >> 3; int o = (seg & 7) * 16;
            cp16(tb + TM * 128 + SWZ128(r * 128 + o),
                 (const char*)(g_wmhT + (size_t)(col0 + r) * LDW + bk) + o);
        }
        asm volatile("cp.async.commit_group;" ::: "memory");
    };

    load_chunk(0, 0); load_chunk(1, 1); load_chunk(2, 2);

    for (int c = 0; c < CH1; c++) {
        int s = c % 3;
        int pend = CH1 - 1 - c;
        if (pend >= 2)      asm volatile("cp.async.wait_group 2;" ::: "memory");
        else if (pend == 1) asm volatile("cp.async.wait_group 1;" ::: "memory");
        else                asm volatile("cp.async.wait_group 0;" ::: "memory");
        __syncthreads();
        const u32 As = tb0 + s * STG, Bs = As + TM * 128;
#pragma unroll
        for (int k16 = 0; k16 < 4; k16++) {
            u32 a[2][4], b[2][2];
#pragma unroll
            for (int mi = 0; mi < 2; mi++) {
                int r = wm0 + mi * 16 + (lane & 15);
                int cb = k16 * 32 + (lane >> 4) * 16;
                u32 ad = As + r * 128 + (cb ^ ((r & 7) << 4));
                asm volatile("ldmatrix.sync.aligned.m8n8.x4.shared.b16 {%0,%1,%2,%3}, [%4];"
                    : "=r"(a[mi][0]), "=r"(a[mi][1]), "=r"(a[mi][2]), "=r"(a[mi][3]) : "r"(ad));
            }
            {
                int l = lane & 7, q = lane >> 3;
                int r = wn0 + (q >> 1) * 8 + l;
                int cb = k16 * 32 + (q & 1) * 16;
                u32 ad = Bs + r * 128 + (cb ^ ((r & 7) << 4));
                asm volatile("ldmatrix.sync.aligned.m8n8.x4.shared.b16 {%0,%1,%2,%3}, [%4];"
                    : "=r"(b[0][0]), "=r"(b[0][1]), "=r"(b[1][0]), "=r"(b[1][1]) : "r"(ad));
            }
#pragma unroll
            for (int mi = 0; mi < 2; mi++)
#pragma unroll
                for (int ni = 0; ni < 2; ni++)
                    asm volatile("mma.sync.aligned.m16n8k16.row.col.f32.f16.f16.f32 "
                        "{%0,%1,%2,%3}, {%4,%5,%6,%7}, {%8,%9}, {%0,%1,%2,%3};"
                        : "+f"(d[mi][ni][0]), "+f"(d[mi][ni][1]),
                          "+f"(d[mi][ni][2]), "+f"(d[mi][ni][3])
                        : "r"(a[mi][0]), "r"(a[mi][1]), "r"(a[mi][2]), "r"(a[mi][3]),
                          "r"(b[ni][0]), "r"(b[ni][1]));
        }
        __syncthreads();
        if (c + 3 < CH1) load_chunk(c + 3, s);
    }

    // epilogue: m = (x@wmx) .* acc
    __syncthreads();
    float* xsh = (float*)tiles;          // [TM][10]
    float* wsh = xsh + TM * 10;          // [10][TN]
    for (int i = tid; i < TM * 10; i += 256)
        xsh[i] = g_xs[((size_t)t * BB + row0 + i / 10) * 10 + (i % 10)];
    for (int i = tid; i < 10 * TN; i += 256)
        wsh[i] = g_wmxp[(i / TN) * NP1 + col0 + (i % TN)];
    __syncthreads();

#pragma unroll
    for (int mi = 0; mi < 2; mi++)
#pragma unroll
        for (int rh = 0; rh < 2; rh++) {
            int rl = wm0 + mi * 16 + (lane >> 2) + rh * 8;
            int r = row0 + rl;
            float xv[10];
#pragma unroll
            for (int e = 0; e < 10; e++) xv[e] = xsh[rl * 10 + e];
#pragma unroll
            for (int ni = 0; ni < 2; ni++)
#pragma unroll
                for (int c2 = 0; c2 < 2; c2++) {
                    int nl = wn0 + ni * 8 + (lane & 3) * 2 + c2;
                    int n = col0 + nl;
                    if (n < H) {
                        float xp = 0.f;
#pragma unroll
                        for (int e = 0; e < 10; e++) xp += xv[e] * wsh[e * TN + nl];
                        float mv = xp * d[mi][ni][rh * 2 + c2];
                        __half hb = __float2half(mv);
                        g_mext[(size_t)r * LDA + n] = hb;
                        g_mext[(size_t)r * LDA + 1920 + n] =
                            __float2half(mv - __half2float(hb));
                    }
                }
        }
}

// ---------------- GEMM2 + gates: 512 thr, tile 128x128, 3 stages, x folded into K ----------------
__global__ void __launch_bounds__(512) gemm2(int t)
{
    constexpr int TM = 128, TN = 128, STG = (TM + TN) * 128;
    extern __shared__ char smraw[];
    char* tiles = (char*)((((u64)smraw) + 1023) & ~(u64)1023);
    const u32 tb0 = smem_u32(tiles);
    const int tid = threadIdx.x, lane = tid & 31, wid = tid >> 5;
    const int wm0 = (wid >> 2) * 32, wn0 = (wid & 3) * 32;
    const int row0 = blockIdx.y * TM, col0 = blockIdx.x * TN;

    float d[2][4][4] = {};

    auto load_chunk = [&](int c, int s) {
        u32 tb = tb0 + s * STG;
        const char *abase, *bbase; size_t astr, bstr;
        if (c < 60) {
            int p = c / 30, kc = c - p * 30;
            int ak = p * 1920 + kc * 64;
            int bk = kc * 64;
            abase = (const char*)(g_mext + (size_t)row0 * LDA + ak); astr = LDA * 2;
            bbase = (const char*)(g_whT + (size_t)col0 * LDW + bk);  bstr = LDW * 2;
        } else {
            abase = (const char*)(g_xext + ((size_t)t * BB + row0) * 64); astr = 128;
            bbase = (const char*)(g_wxext + (size_t)col0 * 64);           bstr = 128;
        }
#pragma unroll
        for (int i = 0; i < 2; i++) {
            int seg = tid + i * 512; int r = seg >> 3; int o = (seg & 7) * 16;
            cp16(tb + SWZ128(r * 128 + o), abase + (size_t)r * astr + o);
        }
#pragma unroll
        for (int i = 0; i < 2; i++) {
            int seg = tid + i * 512; int r = seg >> 3; int o = (seg & 7) * 16;
            cp16(tb + TM * 128 + SWZ128(r * 128 + o), bbase + (size_t)r * bstr + o);
        }
        asm volatile("cp.async.commit_group;" ::: "memory");
    };

    load_chunk(0, 0); load_chunk(1, 1); load_chunk(2, 2);

    for (int c = 0; c < CH2; c++) {
        int s = c % 3;
        int pend = CH2 - 1 - c;
        if (pend >= 2)      asm volatile("cp.async.wait_group 2;" ::: "memory");
        else if (pend == 1) asm volatile("cp.async.wait_group 1;" ::: "memory");
        else                asm volatile("cp.async.wait_group 0;" ::: "memory");
        __syncthreads();
        const u32 As = tb0 + s * STG, Bs = As + TM * 128;
#pragma unroll
        for (int k16 = 0; k16 < 4; k16++) {
            u32 a[2][4], b[4][2];
#pragma unroll
            for (int mi = 0; mi < 2; mi++) {
                int r = wm0 + mi * 16 + (lane & 15);
                int cb = k16 * 32 + (lane >> 4) * 16;
                u32 ad = As + r * 128 + (cb ^ ((r & 7) << 4));
                asm volatile("ldmatrix.sync.aligned.m8n8.x4.shared.b16 {%0,%1,%2,%3}, [%4];"
                    : "=r"(a[mi][0]), "=r"(a[mi][1]), "=r"(a[mi][2]), "=r"(a[mi][3]) : "r"(ad));
            }
#pragma unroll
            for (int nb = 0; nb < 2; nb++) {
                int l = lane & 7, q = lane >> 3;
                int r = wn0 + nb * 16 + (q >> 1) * 8 + l;
                int cb = k16 * 32 + (q & 1) * 16;
                u32 ad = Bs + r * 128 + (cb ^ ((r & 7) << 4));
                asm volatile("ldmatrix.sync.aligned.m8n8.x4.shared.b16 {%0,%1,%2,%3}, [%4];"
                    : "=r"(b[nb*2][0]), "=r"(b[nb*2][1]), "=r"(b[nb*2+1][0]), "=r"(b[nb*2+1][1]) : "r"(ad));
            }
#pragma unroll
            for (int mi = 0; mi < 2; mi++)
#pragma unroll
                for (int ni = 0; ni < 4; ni++)
                    asm volatile("mma.sync.aligned.m16n8k16.row.col.f32.f16.f16.f32 "
                        "{%0,%1,%2,%3}, {%4,%5,%6,%7}, {%8,%9}, {%0,%1,%2,%3};"
                        : "+f"(d[mi][ni][0]), "+f"(d[mi][ni][1]),
                          "+f"(d[mi][ni][2]), "+f"(d[mi][ni][3])
                        : "r"(a[mi][0]), "r"(a[mi][1]), "r"(a[mi][2]), "r"(a[mi][3]),
                          "r"(b[ni][0]), "r"(b[ni][1]));
        }
        __syncthreads();
        if (c + 3 < CH2) load_chunk(c + 3, s);
    }

    // ---- epilogue: exchange accs via smem, then full LSTM gate math ----
    __syncthreads();
    float* zt = (float*)tiles;   // [128][128] f32 = 64KB (stage region reuse)
#pragma unroll
    for (int mi = 0; mi < 2; mi++)
#pragma unroll
        for (int rh = 0; rh < 2; rh++) {
            int r = wm0 + mi * 16 + (lane >> 2) + rh * 8;
#pragma unroll
            for (int ni = 0; ni < 4; ni++) {
                int col = wn0 + ni * 8 + (lane & 3) * 2;
                *(float2*)&zt[r * 128 + col] =
                    make_float2(d[mi][ni][rh * 2], d[mi][ni][rh * 2 + 1]);
            }
        }
    __syncthreads();

    const int u = tid & 31, rgrp = tid >> 5;
    const int j = blockIdx.x * 32 + u;        // hidden unit (interleave: cols 4j+g)
    const bool jv = (j < H);
#pragma unroll
    for (int k = 0; k < 8; k++) {
        int r = rgrp + 16 * k;
        float4 q = *(float4*)&zt[r * 128 + u * 4];   // i, f, o, u
        if (jv) {
            int row = row0 + r;
            float c = g_c[row * NP1 + j];
            c = sigmf(q.y) * c + sigmf(q.x) * tanhf(q.w);
            float h = sigmf(q.z) * tanhf(c);
            g_c[row * NP1 + j] = c;
            __half hb = __float2half(h);
            g_hext[(size_t)row * LDA + j] = hb;
            g_hext[(size_t)row * LDA + 1920 + j] = __float2half(h - __half2float(hb));
            if (row < NB) { if (g_ti[row] == t) g_toth[row * H + j] = h; }
            else { int b2 = row - NB; if (g_ei[b2] == t) g_epih[b2 * H + j] = h; }
        }
    }
}

// ---------------- classifier ----------------
__global__ void classifier_kernel(
    const float* __restrict__ bn1g, const float* __restrict__ bn1b,
    const float* __restrict__ bn1m, const float* __restrict__ bn1v,
    const float* __restrict__ W1,  const float* __restrict__ b1,
    const float* __restrict__ bn2g, const float* __restrict__ bn2b,
    const float* __restrict__ bn2m, const float* __restrict__ bn2v,
    const float* __restrict__ W2,  const float* __restrict__ b2,
    float* __restrict__ out)
{
    __shared__ float xsh[2 * H];
    __shared__ float ysh[380];
    __shared__ float red[256];
    const int b = blockIdx.x, tid = threadIdx.x;
    const int IC = 2 * H, OC = 380;
    for (int k = tid; k < IC; k += 256) {
        float v = (k < H) ? g_toth[b * H + k] : g_epih[b * H + (k - H)];
        v = (v >= 0.f) ? v : 0.3f * v;
        v = (v - bn1m[k]) / sqrtf(bn1v[k] + 1e-3f) * bn1g[k] + bn1b[k];
        xsh[k] = v;
    }
    __syncthreads();
    for (int col = tid; col < OC; col += 256) {
        float s = b1[col];
        for (int k = 0; k < IC; k++) s += xsh[k] * W1[k * OC + col];
        s = (s >= 0.f) ? s : 0.3f * s;
        s = (s - bn2m[col]) / sqrtf(bn2v[col] + 1e-3f) * bn2g[col] + bn2b[col];
        ysh[col] = s;
    }
    __syncthreads();
    float acc = 0.f;
    for (int k = tid; k < OC; k += 256) acc += ysh[k] * W2[k];
    red[tid] = acc;
    __syncthreads();
    for (int s = 128; s > 0; s >>= 1) { if (tid < s) red[tid] += red[tid + s]; __syncthreads(); }
    if (tid == 0) out[b] = red[0] + b2[0];
}

// ---------------- launch ----------------
extern "C" void kernel_launch(void* const* d_in, const int* in_sizes, int n_in,
                              void* d_out, int out_size)
{
    const int*   epi   = (const int*)  d_in[0];
    const int*   lft   = (const int*)  d_in[1];
    const int*   rgt   = (const int*)  d_in[2];
    const int*   tot   = (const int*)  d_in[3];
    const float* embed = (const float*)d_in[4];
    const float* wx    = (const float*)d_in[5];
    const float* wh    = (const float*)d_in[6];
    const float* wmx   = (const float*)d_in[7];
    const float* wmh   = (const float*)d_in[8];
    const float* bb    = (const float*)d_in[9];
    const float* gx    = (const float*)d_in[10];
    const float* gh    = (const float*)d_in[11];
    const float* gmx   = (const float*)d_in[12];
    const float* gmh   = (const float*)d_in[13];
    float* out = (float*)d_out;

    const int SM1 = 1024 + 3 * (64 + 64) * 128;     // ~49 KB
    const int SM2 = 1024 + 3 * (128 + 128) * 128;   // ~97 KB
    cudaFuncSetAttribute(gemm1, cudaFuncAttributeMaxDynamicSharedMemorySize, SM1);
    cudaFuncSetAttribute(gemm2, cudaFuncAttributeMaxDynamicSharedMemorySize, SM2);

    wnormT_kernel<<<(NP2 + 63) / 64, 64>>>(wh, gh, 0);
    wnormT_kernel<<<(NP1 + 63) / 64, 64>>>(wmh, gmh, 1);
    wmx_kernel<<<(NP1 + 127) / 128, 128>>>(wmx, gmx);
    wxext_kernel<<<(NP2 + 127) / 128, 128>>>(wx, gx, bb);
    lengths_kernel<<<1, 256>>>(epi, lft, rgt);
    embed_kernel<<<(TST * BB + 255) / 256, 256>>>(epi, tot, embed);
    init_kernel<<<(BB * NP1 + 255) / 256, 256>>>();

    for (int t = 0; t < TST; t++) {
        const int Mt = (t < TEPI) ? BB : NB;
        gemm1<<<dim3(NP1 / 64, Mt / 64), 256, SM1>>>(t);
        gemm2<<<dim3(NP2 / 128, Mt / 128), 512, SM2>>>(t);
    }

    classifier_kernel<<<NB, 256>>>(
        (const float*)d_in[14], (const float*)d_in[15], (const float*)d_in[16], (const float*)d_in[17],
        (const float*)d_in[18], (const float*)d_in[19],
        (const float*)d_in[20], (const float*)d_in[21], (const float*)d_in[22], (const float*)d_in[23],
        (const float*)d_in[24], (const float*)d_in[25], out);
}

// round 15
// speedup vs baseline: 2.5980x; 1.7429x over previous
#include <cuda_runtime.h>
#include <cuda_fp16.h>
#include <math.h>

typedef unsigned int u32;
typedef unsigned long long u64;

#define H      1900
#define NB     256
#define BB     512
#define TST    153
#define TEPI   25
#define PADTOK 26
#define LDA    1920      // activation K stride (single fp16 plane)
#define LDW    1920      // weight K stride (single fp16 plane)
#define NP1    1920
#define NP2    7680
#define CH1    30        // GEMM1 chunks: 1 pass x 30 chunks of K=64
#define CH2    31        // GEMM2: + 1 x-ext chunk

// ---------------- device scratch ----------------
__device__ __align__(16) __half g_whT [(size_t)NP2 * LDW]; // gate-interleaved [p=4j+g][k]
__device__ __align__(16) __half g_wmhT[(size_t)NP1 * LDW];
__device__ __align__(16) __half g_hext[(size_t)BB * LDA];
__device__ __align__(16) __half g_mext[(size_t)BB * LDA];
__device__ __align__(16) __half g_xext[(size_t)TST * BB * 64]; // per-step x packet
__device__ __align__(16) __half g_wxext[(size_t)NP2 * 64];    // wx/bias packet (interleaved cols)
__device__ __align__(16) float g_c[BB * NP1];
__device__ __align__(16) float g_wmxp[10 * NP1];
__device__ __align__(16) float g_xs[(size_t)TST * BB * 10];
__device__ __align__(16) float g_toth[NB * H];
__device__ __align__(16) float g_epih[NB * H];
__device__ int g_ei[NB];
__device__ int g_ti[NB];

// ---------------- helpers ----------------
__device__ __forceinline__ u32 smem_u32(const void* p) {
    u32 a;
    asm("{ .reg .u64 t; cvta.to.shared.u64 t, %1; cvt.u32.u64 %0, t; }" : "=r"(a) : "l"(p));
    return a;
}
#define SWZ128(o) ((u32)(o) ^ ((((u32)(o)) >> 3) & 0x70u))
__device__ __forceinline__ void cp16(u32 dst, const void* src) {
    asm volatile("cp.async.cg.shared.global [%0], [%1], 16;" :: "r"(dst), "l"(src) : "memory");
}
__device__ __forceinline__ float sigmf(float x) { return 1.f / (1.f + expf(-x)); }

// ---------------- prep kernels ----------------
__global__ void wnormT_kernel(const float* __restrict__ w, const float* __restrict__ g, int mode)
{
    // mode 0: wh [1900,7600] -> g_whT gate-interleaved ; mode 1: wmh [1900,1900] -> g_wmhT
    int p = blockIdx.x * blockDim.x + threadIdx.x;
    const int NP = mode ? NP1 : NP2;
    if (p >= NP) return;
    __half* out = (mode ? g_wmhT : g_whT) + (size_t)p * LDW;
    int n; bool valid;
    if (mode) { n = p; valid = (p < 1900); }
    else      { int j = p >> 2, gg = p & 3; n = gg * 1900 + j; valid = (j < 1900); }
    const int N = mode ? 1900 : 7600;
    if (!valid) { u32* o = (u32*)out; for (int i = 0; i < LDW / 2; i++) o[i] = 0u; return; }
    float s = 0.f;
    for (int k = 0; k < 1900; k++) { float v = w[(size_t)k * N + n]; s += v * v; }
    float sc = g[n] * rsqrtf(fmaxf(s, 1e-12f));
    for (int k0 = 0; k0 < LDW; k0 += 8) {
        union { __half b[8]; uint4 v; } Hi;
#pragma unroll
        for (int e = 0; e < 8; e++) {
            int k = k0 + e;
            float v = (k < 1900) ? w[(size_t)k * N + n] * sc : 0.f;
            Hi.b[e] = __float2half(v);
        }
        *(uint4*)(out + k0) = Hi.v;
    }
}

__global__ void wmx_kernel(const float* __restrict__ w, const float* __restrict__ g)
{
    int n = blockIdx.x * blockDim.x + threadIdx.x;
    if (n >= NP1) return;
    if (n >= 1900) { for (int k = 0; k < 10; k++) g_wmxp[k * NP1 + n] = 0.f; return; }
    float s = 0.f;
    for (int k = 0; k < 10; k++) { float v = w[k * 1900 + n]; s += v * v; }
    float sc = g[n] * rsqrtf(fmaxf(s, 1e-12f));
    for (int k = 0; k < 10; k++) g_wmxp[k * NP1 + n] = w[k * 1900 + n] * sc;
}

__global__ void wxext_kernel(const float* __restrict__ wx, const float* __restrict__ gx,
                             const float* __restrict__ b)
{
    // g_wxext[p][0..9]=wx  [10..19]=wx  [20]=b_hi [21]=b_lo  rest 0
    int p = blockIdx.x * blockDim.x + threadIdx.x;
    if (p >= NP2) return;
    __half* out = g_wxext + (size_t)p * 64;
    int j = p >> 2, gg = p & 3, n = gg * 1900 + j;
    for (int k = 0; k < 64; k++) out[k] = __float2half(0.f);
    if (j >= 1900) return;
    float s = 0.f;
    for (int k = 0; k < 10; k++) { float v = wx[k * 7600 + n]; s += v * v; }
    float sc = gx[n] * rsqrtf(fmaxf(s, 1e-12f));
    for (int e = 0; e < 10; e++) {
        float v = wx[e * 7600 + n] * sc;
        __half hb = __float2half(v);
        out[e] = hb;
        out[10 + e] = hb;
    }
    float bv = b[n];
    __half bh = __float2half(bv);
    out[20] = bh;
    out[21] = __float2half(bv - __half2float(bh));
}

__global__ void lengths_kernel(const int* __restrict__ epi, const int* __restrict__ lft,
                               const int* __restrict__ rgt)
{
    int b = blockIdx.x * blockDim.x + threadIdx.x;
    if (b >= NB) return;
    int el = 0; for (int t = 0; t < TEPI; t++) el += (epi[b * TEPI + t] != PADTOK);
    int ll = 0; for (int t = 0; t < 64;   t++) ll += (lft[b * 64 + t]   != PADTOK);
    int rl = 0; for (int t = 0; t < 64;   t++) rl += (rgt[b * 64 + t]   != PADTOK);
    ll = max(ll, 1); rl = max(rl, 1);
    int tl = el + ll + rl;
    g_ei[b] = min(max(el - 1, 0), TEPI - 1);
    g_ti[b] = min(max(tl - 1, 0), TST - 1);
}

__global__ void embed_kernel(const int* __restrict__ epi, const int* __restrict__ tot,
                             const float* __restrict__ embed)
{
    int idx = blockIdx.x * blockDim.x + threadIdx.x;
    if (idx >= TST * BB) return;
    int t = idx / BB, row = idx % BB;
    int tok;
    if (row < NB) tok = tot[row * TST + t];
    else { if (t >= TEPI) return; tok = epi[(row - NB) * TEPI + t]; }
    float x[10];
    for (int e = 0; e < 10; e++) x[e] = embed[tok * 10 + e];
    float* xs = &g_xs[(size_t)idx * 10];
    for (int e = 0; e < 10; e++) xs[e] = x[e];
    __half* xe = &g_xext[(size_t)idx * 64];
    for (int k = 0; k < 64; k++) xe[k] = __float2half(0.f);
    for (int e = 0; e < 10; e++) {
        __half hb = __float2half(x[e]);
        xe[e] = hb;
        xe[10 + e] = __float2half(x[e] - __half2float(hb));
    }
    xe[20] = __float2half(1.f);
    xe[21] = __float2half(1.f);
}

__global__ void init_kernel()
{
    int i = blockIdx.x * blockDim.x + threadIdx.x;
    if (i < BB * NP1) {
        g_c[i] = 0.f;
        if (i < BB * NP1 / 2) { ((u32*)g_hext)[i] = 0u; ((u32*)g_mext)[i] = 0u; }
    }
}

// ---------------- GEMM1: m = (x@wmx) .* (h@wmh) ; 256 thr, tile 64x64, 3 stages ----------------
__global__ void __launch_bounds__(256) gemm1(int t)
{
    constexpr int TM = 64, TN = 64, STG = (TM + TN) * 128;
    extern __shared__ char smraw[];
    char* tiles = (char*)((((u64)smraw) + 1023) & ~(u64)1023);
    const u32 tb0 = smem_u32(tiles);
    const int tid = threadIdx.x, lane = tid & 31, wid = tid >> 5;
    const int wm0 = (wid >> 2) * 32, wn0 = (wid & 3) * 16;
    const int row0 = blockIdx.y * TM, col0 = blockIdx.x * TN;

    float d[2][2][4] = {};

    auto load_chunk = [&](int c, int s) {
        int ak = c * 64;
        int bk = c * 64;
        u32 tb = tb0 + s * STG;
#pragma unroll
        for (int i = 0; i < 2; i++) {
            int seg = tid + i * 256; int r = seg >> 3; int o = (seg & 7) * 16;
            cp16(tb + SWZ128(r * 128 + o),
                 (const char*)(g_hext + (size_t)(row0 + r) * LDA + ak) + o);
        }
#pragma unroll
        for (int i = 0; i < 2; i++) {
            int seg = tid + i * 256; int r = seg >> 3; int o = (seg & 7) * 16;
            cp16(tb + TM * 128 + SWZ128(r * 128 + o),
                 (const char*)(g_wmhT + (size_t)(col0 + r) * LDW + bk) + o);
        }
        asm volatile("cp.async.commit_group;" ::: "memory");
    };

    load_chunk(0, 0); load_chunk(1, 1); load_chunk(2, 2);

    for (int c = 0; c < CH1; c++) {
        int s = c % 3;
        int pend = CH1 - 1 - c;
        if (pend >= 2)      asm volatile("cp.async.wait_group 2;" ::: "memory");
        else if (pend == 1) asm volatile("cp.async.wait_group 1;" ::: "memory");
        else                asm volatile("cp.async.wait_group 0;" ::: "memory");
        __syncthreads();
        const u32 As = tb0 + s * STG, Bs = As + TM * 128;
#pragma unroll
        for (int k16 = 0; k16 < 4; k16++) {
            u32 a[2][4], b[2][2];
#pragma unroll
            for (int mi = 0; mi < 2; mi++) {
                int r = wm0 + mi * 16 + (lane & 15);
                int cb = k16 * 32 + (lane >> 4) * 16;
                u32 ad = As + r * 128 + (cb ^ ((r & 7) << 4));
                asm volatile("ldmatrix.sync.aligned.m8n8.x4.shared.b16 {%0,%1,%2,%3}, [%4];"
                    : "=r"(a[mi][0]), "=r"(a[mi][1]), "=r"(a[mi][2]), "=r"(a[mi][3]) : "r"(ad));
            }
            {
                int l = lane & 7, q = lane >> 3;
                int r = wn0 + (q >> 1) * 8 + l;
                int cb = k16 * 32 + (q & 1) * 16;
                u32 ad = Bs + r * 128 + (cb ^ ((r & 7) << 4));
                asm volatile("ldmatrix.sync.aligned.m8n8.x4.shared.b16 {%0,%1,%2,%3}, [%4];"
                    : "=r"(b[0][0]), "=r"(b[0][1]), "=r"(b[1][0]), "=r"(b[1][1]) : "r"(ad));
            }
#pragma unroll
            for (int mi = 0; mi < 2; mi++)
#pragma unroll
                for (int ni = 0; ni < 2; ni++)
                    asm volatile("mma.sync.aligned.m16n8k16.row.col.f32.f16.f16.f32 "
                        "{%0,%1,%2,%3}, {%4,%5,%6,%7}, {%8,%9}, {%0,%1,%2,%3};"
                        : "+f"(d[mi][ni][0]), "+f"(d[mi][ni][1]),
                          "+f"(d[mi][ni][2]), "+f"(d[mi][ni][3])
                        : "r"(a[mi][0]), "r"(a[mi][1]), "r"(a[mi][2]), "r"(a[mi][3]),
                          "r"(b[ni][0]), "r"(b[ni][1]));
        }
        __syncthreads();
        if (c + 3 < CH1) load_chunk(c + 3, s);
    }

    // epilogue: m = (x@wmx) .* acc
    __syncthreads();
    float* xsh = (float*)tiles;          // [TM][10]
    float* wsh = xsh + TM * 10;          // [10][TN]
    for (int i = tid; i < TM * 10; i += 256)
        xsh[i] = g_xs[((size_t)t * BB + row0 + i / 10) * 10 + (i % 10)];
    for (int i = tid; i < 10 * TN; i += 256)
        wsh[i] = g_wmxp[(i / TN) * NP1 + col0 + (i % TN)];
    __syncthreads();

#pragma unroll
    for (int mi = 0; mi < 2; mi++)
#pragma unroll
        for (int rh = 0; rh < 2; rh++) {
            int rl = wm0 + mi * 16 + (lane >> 2) + rh * 8;
            int r = row0 + rl;
            float xv[10];
#pragma unroll
            for (int e = 0; e < 10; e++) xv[e] = xsh[rl * 10 + e];
#pragma unroll
            for (int ni = 0; ni < 2; ni++)
#pragma unroll
                for (int c2 = 0; c2 < 2; c2++) {
                    int nl = wn0 + ni * 8 + (lane & 3) * 2 + c2;
                    int n = col0 + nl;
                    if (n < H) {
                        float xp = 0.f;
#pragma unroll
                        for (int e = 0; e < 10; e++) xp += xv[e] * wsh[e * TN + nl];
                        float mv = xp * d[mi][ni][rh * 2 + c2];
                        g_mext[(size_t)r * LDA + n] = __float2half(mv);
                    }
                }
        }
}

// ---------------- GEMM2 + gates: 512 thr, tile 128x128, 3 stages, x folded into K ----------------
__global__ void __launch_bounds__(512) gemm2(int t)
{
    constexpr int TM = 128, TN = 128, STG = (TM + TN) * 128;
    extern __shared__ char smraw[];
    char* tiles = (char*)((((u64)smraw) + 1023) & ~(u64)1023);
    const u32 tb0 = smem_u32(tiles);
    const int tid = threadIdx.x, lane = tid & 31, wid = tid >> 5;
    const int wm0 = (wid >> 2) * 32, wn0 = (wid & 3) * 32;
    const int row0 = blockIdx.y * TM, col0 = blockIdx.x * TN;

    float d[2][4][4] = {};

    auto load_chunk = [&](int c, int s) {
        u32 tb = tb0 + s * STG;
        const char *abase, *bbase; size_t astr, bstr;
        if (c < 30) {
            int ak = c * 64;
            int bk = c * 64;
            abase = (const char*)(g_mext + (size_t)row0 * LDA + ak); astr = LDA * 2;
            bbase = (const char*)(g_whT + (size_t)col0 * LDW + bk);  bstr = LDW * 2;
        } else {
            abase = (const char*)(g_xext + ((size_t)t * BB + row0) * 64); astr = 128;
            bbase = (const char*)(g_wxext + (size_t)col0 * 64);           bstr = 128;
        }
#pragma unroll
        for (int i = 0; i < 2; i++) {
            int seg = tid + i * 512; int r = seg >> 3; int o = (seg & 7) * 16;
            cp16(tb + SWZ128(r * 128 + o), abase + (size_t)r * astr + o);
        }
#pragma unroll
        for (int i = 0; i < 2; i++) {
            int seg = tid + i * 512; int r = seg >> 3; int o = (seg & 7) * 16;
            cp16(tb + TM * 128 + SWZ128(r * 128 + o), bbase + (size_t)r * bstr + o);
        }
        asm volatile("cp.async.commit_group;" ::: "memory");
    };

    load_chunk(0, 0); load_chunk(1, 1); load_chunk(2, 2);

    for (int c = 0; c < CH2; c++) {
        int s = c % 3;
        int pend = CH2 - 1 - c;
        if (pend >= 2)      asm volatile("cp.async.wait_group 2;" ::: "memory");
        else if (pend == 1) asm volatile("cp.async.wait_group 1;" ::: "memory");
        else                asm volatile("cp.async.wait_group 0;" ::: "memory");
        __syncthreads();
        const u32 As = tb0 + s * STG, Bs = As + TM * 128;
#pragma unroll
        for (int k16 = 0; k16 < 4; k16++) {
            u32 a[2][4], b[4][2];
#pragma unroll
            for (int mi = 0; mi < 2; mi++) {
                int r = wm0 + mi * 16 + (lane & 15);
                int cb = k16 * 32 + (lane >> 4) * 16;
                u32 ad = As + r * 128 + (cb ^ ((r & 7) << 4));
                asm volatile("ldmatrix.sync.aligned.m8n8.x4.shared.b16 {%0,%1,%2,%3}, [%4];"
                    : "=r"(a[mi][0]), "=r"(a[mi][1]), "=r"(a[mi][2]), "=r"(a[mi][3]) : "r"(ad));
            }
#pragma unroll
            for (int nb = 0; nb < 2; nb++) {
                int l = lane & 7, q = lane >> 3;
                int r = wn0 + nb * 16 + (q >> 1) * 8 + l;
                int cb = k16 * 32 + (q & 1) * 16;
                u32 ad = Bs + r * 128 + (cb ^ ((r & 7) << 4));
                asm volatile("ldmatrix.sync.aligned.m8n8.x4.shared.b16 {%0,%1,%2,%3}, [%4];"
                    : "=r"(b[nb*2][0]), "=r"(b[nb*2][1]), "=r"(b[nb*2+1][0]), "=r"(b[nb*2+1][1]) : "r"(ad));
            }
#pragma unroll
            for (int mi = 0; mi < 2; mi++)
#pragma unroll
                for (int ni = 0; ni < 4; ni++)
                    asm volatile("mma.sync.aligned.m16n8k16.row.col.f32.f16.f16.f32 "
                        "{%0,%1,%2,%3}, {%4,%5,%6,%7}, {%8,%9}, {%0,%1,%2,%3};"
                        : "+f"(d[mi][ni][0]), "+f"(d[mi][ni][1]),
                          "+f"(d[mi][ni][2]), "+f"(d[mi][ni][3])
                        : "r"(a[mi][0]), "r"(a[mi][1]), "r"(a[mi][2]), "r"(a[mi][3]),
                          "r"(b[ni][0]), "r"(b[ni][1]));
        }
        __syncthreads();
        if (c + 3 < CH2) load_chunk(c + 3, s);
    }

    // ---- epilogue: exchange accs via smem, then full LSTM gate math ----
    __syncthreads();
    float* zt = (float*)tiles;   // [128][128] f32 = 64KB (stage region reuse)
#pragma unroll
    for (int mi = 0; mi < 2; mi++)
#pragma unroll
        for (int rh = 0; rh < 2; rh++) {
            int r = wm0 + mi * 16 + (lane >> 2) + rh * 8;
#pragma unroll
            for (int ni = 0; ni < 4; ni++) {
                int col = wn0 + ni * 8 + (lane & 3) * 2;
                *(float2*)&zt[r * 128 + col] =
                    make_float2(d[mi][ni][rh * 2], d[mi][ni][rh * 2 + 1]);
            }
        }
    __syncthreads();

    const int u = tid & 31, rgrp = tid >> 5;
    const int j = blockIdx.x * 32 + u;        // hidden unit (interleave: cols 4j+g)
    const bool jv = (j < H);
#pragma unroll
    for (int k = 0; k < 8; k++) {
        int r = rgrp + 16 * k;
        float4 q = *(float4*)&zt[r * 128 + u * 4];   // i, f, o, u
        if (jv) {
            int row = row0 + r;
            float c = g_c[row * NP1 + j];
            c = sigmf(q.y) * c + sigmf(q.x) * tanhf(q.w);
            float h = sigmf(q.z) * tanhf(c);
            g_c[row * NP1 + j] = c;
            g_hext[(size_t)row * LDA + j] = __float2half(h);
            if (row < NB) { if (g_ti[row] == t) g_toth[row * H + j] = h; }
            else { int b2 = row - NB; if (g_ei[b2] == t) g_epih[b2 * H + j] = h; }
        }
    }
}

// ---------------- classifier ----------------
__global__ void classifier_kernel(
    const float* __restrict__ bn1g, const float* __restrict__ bn1b,
    const float* __restrict__ bn1m, const float* __restrict__ bn1v,
    const float* __restrict__ W1,  const float* __restrict__ b1,
    const float* __restrict__ bn2g, const float* __restrict__ bn2b,
    const float* __restrict__ bn2m, const float* __restrict__ bn2v,
    const float* __restrict__ W2,  const float* __restrict__ b2,
    float* __restrict__ out)
{
    __shared__ float xsh[2 * H];
    __shared__ float ysh[380];
    __shared__ float red[256];
    const int b = blockIdx.x, tid = threadIdx.x;
    const int IC = 2 * H, OC = 380;
    for (int k = tid; k < IC; k += 256) {
        float v = (k < H) ? g_toth[b * H + k] : g_epih[b * H + (k - H)];
        v = (v >= 0.f) ? v : 0.3f * v;
        v = (v - bn1m[k]) / sqrtf(bn1v[k] + 1e-3f) * bn1g[k] + bn1b[k];
        xsh[k] = v;
    }
    __syncthreads();
    for (int col = tid; col < OC; col += 256) {
        float s = b1[col];
        for (int k = 0; k < IC; k++) s += xsh[k] * W1[k * OC + col];
        s = (s >= 0.f) ? s : 0.3f * s;
        s = (s - bn2m[col]) / sqrtf(bn2v[col] + 1e-3f) * bn2g[col] + bn2b[col];
        ysh[col] = s;
    }
    __syncthreads();
    float acc = 0.f;
    for (int k = tid; k < OC; k += 256) acc += ysh[k] * W2[k];
    red[tid] = acc;
    __syncthreads();
    for (int s = 128; s > 0; s >>= 1) { if (tid < s) red[tid] += red[tid + s]; __syncthreads(); }
    if (tid == 0) out[b] = red[0] + b2[0];
}

// ---------------- launch ----------------
extern "C" void kernel_launch(void* const* d_in, const int* in_sizes, int n_in,
                              void* d_out, int out_size)
{
    const int*   epi   = (const int*)  d_in[0];
    const int*   lft   = (const int*)  d_in[1];
    const int*   rgt   = (const int*)  d_in[2];
    const int*   tot   = (const int*)  d_in[3];
    const float* embed = (const float*)d_in[4];
    const float* wx    = (const float*)d_in[5];
    const float* wh    = (const float*)d_in[6];
    const float* wmx   = (const float*)d_in[7];
    const float* wmh   = (const float*)d_in[8];
    const float* bb    = (const float*)d_in[9];
    const float* gx    = (const float*)d_in[10];
    const float* gh    = (const float*)d_in[11];
    const float* gmx   = (const float*)d_in[12];
    const float* gmh   = (const float*)d_in[13];
    float* out = (float*)d_out;

    const int SM1 = 1024 + 3 * (64 + 64) * 128;     // ~49 KB
    const int SM2 = 1024 + 3 * (128 + 128) * 128;   // ~97 KB
    cudaFuncSetAttribute(gemm1, cudaFuncAttributeMaxDynamicSharedMemorySize, SM1);
    cudaFuncSetAttribute(gemm2, cudaFuncAttributeMaxDynamicSharedMemorySize, SM2);

    wnormT_kernel<<<(NP2 + 63) / 64, 64>>>(wh, gh, 0);
    wnormT_kernel<<<(NP1 + 63) / 64, 64>>>(wmh, gmh, 1);
    wmx_kernel<<<(NP1 + 127) / 128, 128>>>(wmx, gmx);
    wxext_kernel<<<(NP2 + 127) / 128, 128>>>(wx, gx, bb);
    lengths_kernel<<<1, 256>>>(epi, lft, rgt);
    embed_kernel<<<(TST * BB + 255) / 256, 256>>>(epi, tot, embed);
    init_kernel<<<(BB * NP1 + 255) / 256, 256>>>();

    for (int t = 0; t < TST; t++) {
        const int Mt = (t < TEPI) ? BB : NB;
        gemm1<<<dim3(NP1 / 64, Mt / 64), 256, SM1>>>(t);
        gemm2<<<dim3(NP2 / 128, Mt / 128), 512, SM2>>>(t);
    }

    classifier_kernel<<<NB, 256>>>(
        (const float*)d_in[14], (const float*)d_in[15], (const float*)d_in[16], (const float*)d_in[17],
        (const float*)d_in[18], (const float*)d_in[19],
        (const float*)d_in[20], (const float*)d_in[21], (const float*)d_in[22], (const float*)d_in[23],
        (const float*)d_in[24], (const float*)d_in[25], out);
}

// round 16
// speedup vs baseline: 2.6763x; 1.0302x over previous
#include <cuda_runtime.h>
#include <cuda_fp16.h>
#include <math.h>

typedef unsigned int u32;
typedef unsigned long long u64;

#define H      1900
#define NB     256
#define BB     512
#define TST    153
#define TEPI   25
#define PADTOK 26
#define LDA    1920      // activation K stride (single fp16 plane)
#define LDW    1920      // weight K stride (single fp16 plane)
#define NP1    1920
#define NP2    7680
#define CH1P   15        // GEMM1: 15 K128 pairs
#define CH2P   16        // GEMM2: 15 K128 pairs + 1 x64 chunk

// ---------------- device scratch ----------------
__device__ __align__(16) __half g_whT [(size_t)NP2 * LDW]; // gate-interleaved [p=4j+g][k]
__device__ __align__(16) __half g_wmhT[(size_t)NP1 * LDW];
__device__ __align__(16) __half g_hext[(size_t)BB * LDA];
__device__ __align__(16) __half g_mext[(size_t)BB * LDA];
__device__ __align__(16) __half g_xext[(size_t)TST * BB * 64]; // per-step x packet
__device__ __align__(16) __half g_wxext[(size_t)NP2 * 64];    // wx/bias packet (interleaved cols)
__device__ __align__(16) float g_c[BB * NP1];
__device__ __align__(16) float g_wmxp[10 * NP1];
__device__ __align__(16) float g_xs[(size_t)TST * BB * 10];
__device__ __align__(16) float g_toth[NB * H];
__device__ __align__(16) float g_epih[NB * H];
__device__ int g_ei[NB];
__device__ int g_ti[NB];

// ---------------- helpers ----------------
__device__ __forceinline__ u32 smem_u32(const void* p) {
    u32 a;
    asm("{ .reg .u64 t; cvta.to.shared.u64 t, %1; cvt.u32.u64 %0, t; }" : "=r"(a) : "l"(p));
    return a;
}
#define SWZ128(o) ((u32)(o) ^ ((((u32)(o)) >> 3) & 0x70u))
__device__ __forceinline__ void cp16(u32 dst, const void* src) {
    asm volatile("cp.async.cg.shared.global [%0], [%1], 16;" :: "r"(dst), "l"(src) : "memory");
}
__device__ __forceinline__ float sigmf(float x) { return 1.f / (1.f + expf(-x)); }

// ---------------- prep kernels ----------------
__global__ void wnormT_kernel(const float* __restrict__ w, const float* __restrict__ g, int mode)
{
    // mode 0: wh [1900,7600] -> g_whT gate-interleaved ; mode 1: wmh [1900,1900] -> g_wmhT
    int p = blockIdx.x * blockDim.x + threadIdx.x;
    const int NP = mode ? NP1 : NP2;
    if (p >= NP) return;
    __half* out = (mode ? g_wmhT : g_whT) + (size_t)p * LDW;
    int n; bool valid;
    if (mode) { n = p; valid = (p < 1900); }
    else      { int j = p >> 2, gg = p & 3; n = gg * 1900 + j; valid = (j < 1900); }
    const int N = mode ? 1900 : 7600;
    if (!valid) { u32* o = (u32*)out; for (int i = 0; i < LDW / 2; i++) o[i] = 0u; return; }
    float s = 0.f;
    for (int k = 0; k < 1900; k++) { float v = w[(size_t)k * N + n]; s += v * v; }
    float sc = g[n] * rsqrtf(fmaxf(s, 1e-12f));
    for (int k0 = 0; k0 < LDW; k0 += 8) {
        union { __half b[8]; uint4 v; } Hi;
#pragma unroll
        for (int e = 0; e < 8; e++) {
            int k = k0 + e;
            float v = (k < 1900) ? w[(size_t)k * N + n] * sc : 0.f;
            Hi.b[e] = __float2half(v);
        }
        *(uint4*)(out + k0) = Hi.v;
    }
}

__global__ void wmx_kernel(const float* __restrict__ w, const float* __restrict__ g)
{
    int n = blockIdx.x * blockDim.x + threadIdx.x;
    if (n >= NP1) return;
    if (n >= 1900) { for (int k = 0; k < 10; k++) g_wmxp[k * NP1 + n] = 0.f; return; }
    float s = 0.f;
    for (int k = 0; k < 10; k++) { float v = w[k * 1900 + n]; s += v * v; }
    float sc = g[n] * rsqrtf(fmaxf(s, 1e-12f));
    for (int k = 0; k < 10; k++) g_wmxp[k * NP1 + n] = w[k * 1900 + n] * sc;
}

__global__ void wxext_kernel(const float* __restrict__ wx, const float* __restrict__ gx,
                             const float* __restrict__ b)
{
    // g_wxext[p][0..9]=wx  [10..19]=wx  [20]=b_hi [21]=b_lo  rest 0
    int p = blockIdx.x * blockDim.x + threadIdx.x;
    if (p >= NP2) return;
    __half* out = g_wxext + (size_t)p * 64;
    int j = p >> 2, gg = p & 3, n = gg * 1900 + j;
    for (int k = 0; k < 64; k++) out[k] = __float2half(0.f);
    if (j >= 1900) return;
    float s = 0.f;
    for (int k = 0; k < 10; k++) { float v = wx[k * 7600 + n]; s += v * v; }
    float sc = gx[n] * rsqrtf(fmaxf(s, 1e-12f));
    for (int e = 0; e < 10; e++) {
        float v = wx[e * 7600 + n] * sc;
        __half hb = __float2half(v);
        out[e] = hb;
        out[10 + e] = hb;
    }
    float bv = b[n];
    __half bh = __float2half(bv);
    out[20] = bh;
    out[21] = __float2half(bv - __half2float(bh));
}

__global__ void lengths_kernel(const int* __restrict__ epi, const int* __restrict__ lft,
                               const int* __restrict__ rgt)
{
    int b = blockIdx.x * blockDim.x + threadIdx.x;
    if (b >= NB) return;
    int el = 0; for (int t = 0; t < TEPI; t++) el += (epi[b * TEPI + t] != PADTOK);
    int ll = 0; for (int t = 0; t < 64;   t++) ll += (lft[b * 64 + t]   != PADTOK);
    int rl = 0; for (int t = 0; t < 64;   t++) rl += (rgt[b * 64 + t]   != PADTOK);
    ll = max(ll, 1); rl = max(rl, 1);
    int tl = el + ll + rl;
    g_ei[b] = min(max(el - 1, 0), TEPI - 1);
    g_ti[b] = min(max(tl - 1, 0), TST - 1);
}

__global__ void embed_kernel(const int* __restrict__ epi, const int* __restrict__ tot,
                             const float* __restrict__ embed)
{
    int idx = blockIdx.x * blockDim.x + threadIdx.x;
    if (idx >= TST * BB) return;
    int t = idx / BB, row = idx % BB;
    int tok;
    if (row < NB) tok = tot[row * TST + t];
    else { if (t >= TEPI) return; tok = epi[(row - NB) * TEPI + t]; }
    float x[10];
    for (int e = 0; e < 10; e++) x[e] = embed[tok * 10 + e];
    float* xs = &g_xs[(size_t)idx * 10];
    for (int e = 0; e < 10; e++) xs[e] = x[e];
    __half* xe = &g_xext[(size_t)idx * 64];
    for (int k = 0; k < 64; k++) xe[k] = __float2half(0.f);
    for (int e = 0; e < 10; e++) {
        __half hb = __float2half(x[e]);
        xe[e] = hb;
        xe[10 + e] = __float2half(x[e] - __half2float(hb));
    }
    xe[20] = __float2half(1.f);
    xe[21] = __float2half(1.f);
}

__global__ void init_kernel()
{
    int i = blockIdx.x * blockDim.x + threadIdx.x;
    if (i < BB * NP1) {
        g_c[i] = 0.f;
        if (i < BB * NP1 / 2) { ((u32*)g_hext)[i] = 0u; ((u32*)g_mext)[i] = 0u; }
    }
}

// ---------------- GEMM1: m = (x@wmx) .* (h@wmh) ; 256 thr, tile 64x64, K128 pairs ----------------
__global__ void __launch_bounds__(256) gemm1(int t)
{
    constexpr int TM = 64, TN = 64;
    constexpr int SUB = (TM + TN) * 128;   // 16 KB per K64 sub-tile
    constexpr int STG = 2 * SUB;           // K128 pair stage
    extern __shared__ char smraw[];
    char* tiles = (char*)((((u64)smraw) + 1023) & ~(u64)1023);
    const u32 tb0 = smem_u32(tiles);
    const int tid = threadIdx.x, lane = tid & 31, wid = tid >> 5;
    const int wm0 = (wid >> 2) * 32, wn0 = (wid & 3) * 16;
    const int row0 = blockIdx.y * TM, col0 = blockIdx.x * TN;

    float d[2][2][4] = {};

    auto load_unit = [&](int unit, u32 tb) {
        int k0 = unit * 64;
#pragma unroll
        for (int i = 0; i < 2; i++) {
            int seg = tid + i * 256; int r = seg >> 3; int o = (seg & 7) * 16;
            cp16(tb + SWZ128(r * 128 + o),
                 (const char*)(g_hext + (size_t)(row0 + r) * LDA + k0) + o);
        }
#pragma unroll
        for (int i = 0; i < 2; i++) {
            int seg = tid + i * 256; int r = seg >> 3; int o = (seg & 7) * 16;
            cp16(tb + TM * 128 + SWZ128(r * 128 + o),
                 (const char*)(g_wmhT + (size_t)(col0 + r) * LDW + k0) + o);
        }
    };
    auto load_pair = [&](int c, int s) {
        load_unit(c * 2, tb0 + s * STG);
        load_unit(c * 2 + 1, tb0 + s * STG + SUB);
        asm volatile("cp.async.commit_group;" ::: "memory");
    };

    load_pair(0, 0); load_pair(1, 1);

    for (int c = 0; c < CH1P; c++) {
        int s = c & 1;
        if (c + 1 < CH1P) asm volatile("cp.async.wait_group 1;" ::: "memory");
        else              asm volatile("cp.async.wait_group 0;" ::: "memory");
        __syncthreads();
#pragma unroll
        for (int sub = 0; sub < 2; sub++) {
            const u32 As = tb0 + s * STG + sub * SUB, Bs = As + TM * 128;
#pragma unroll
            for (int k16 = 0; k16 < 4; k16++) {
                u32 a[2][4], b[2][2];
#pragma unroll
                for (int mi = 0; mi < 2; mi++) {
                    int r = wm0 + mi * 16 + (lane & 15);
                    int cb = k16 * 32 + (lane >> 4) * 16;
                    u32 ad = As + r * 128 + (cb ^ ((r & 7) << 4));
                    asm volatile("ldmatrix.sync.aligned.m8n8.x4.shared.b16 {%0,%1,%2,%3}, [%4];"
                        : "=r"(a[mi][0]), "=r"(a[mi][1]), "=r"(a[mi][2]), "=r"(a[mi][3]) : "r"(ad));
                }
                {
                    int l = lane & 7, q = lane >> 3;
                    int r = wn0 + (q >> 1) * 8 + l;
                    int cb = k16 * 32 + (q & 1) * 16;
                    u32 ad = Bs + r * 128 + (cb ^ ((r & 7) << 4));
                    asm volatile("ldmatrix.sync.aligned.m8n8.x4.shared.b16 {%0,%1,%2,%3}, [%4];"
                        : "=r"(b[0][0]), "=r"(b[0][1]), "=r"(b[1][0]), "=r"(b[1][1]) : "r"(ad));
                }
#pragma unroll
                for (int mi = 0; mi < 2; mi++)
#pragma unroll
                    for (int ni = 0; ni < 2; ni++)
                        asm volatile("mma.sync.aligned.m16n8k16.row.col.f32.f16.f16.f32 "
                            "{%0,%1,%2,%3}, {%4,%5,%6,%7}, {%8,%9}, {%0,%1,%2,%3};"
                            : "+f"(d[mi][ni][0]), "+f"(d[mi][ni][1]),
                              "+f"(d[mi][ni][2]), "+f"(d[mi][ni][3])
                            : "r"(a[mi][0]), "r"(a[mi][1]), "r"(a[mi][2]), "r"(a[mi][3]),
                              "r"(b[ni][0]), "r"(b[ni][1]));
            }
        }
        __syncthreads();
        if (c + 2 < CH1P) load_pair(c + 2, s);
    }

    // epilogue: m = (x@wmx) .* acc
    __syncthreads();
    float* xsh = (float*)tiles;          // [TM][10]
    float* wsh = xsh + TM * 10;          // [10][TN]
    for (int i = tid; i < TM * 10; i += 256)
        xsh[i] = g_xs[((size_t)t * BB + row0 + i / 10) * 10 + (i % 10)];
    for (int i = tid; i < 10 * TN; i += 256)
        wsh[i] = g_wmxp[(i / TN) * NP1 + col0 + (i % TN)];
    __syncthreads();

#pragma unroll
    for (int mi = 0; mi < 2; mi++)
#pragma unroll
        for (int rh = 0; rh < 2; rh++) {
            int rl = wm0 + mi * 16 + (lane >> 2) + rh * 8;
            int r = row0 + rl;
            float xv[10];
#pragma unroll
            for (int e = 0; e < 10; e++) xv[e] = xsh[rl * 10 + e];
#pragma unroll
            for (int ni = 0; ni < 2; ni++)
#pragma unroll
                for (int c2 = 0; c2 < 2; c2++) {
                    int nl = wn0 + ni * 8 + (lane & 3) * 2 + c2;
                    int n = col0 + nl;
                    if (n < H) {
                        float xp = 0.f;
#pragma unroll
                        for (int e = 0; e < 10; e++) xp += xv[e] * wsh[e * TN + nl];
                        float mv = xp * d[mi][ni][rh * 2 + c2];
                        g_mext[(size_t)r * LDA + n] = __float2half(mv);
                    }
                }
        }
}

// ---------------- GEMM2 + gates: 256 thr, tile 128x128, warp tile 32x64, K128 pairs ----------------
__global__ void __launch_bounds__(256) gemm2(int t)
{
    constexpr int SUB = 256 * 128;       // 32 KB per K64 sub-tile (A 16K + B 16K)
    constexpr int STG = 2 * SUB;         // K128 pair stage = 64 KB
    extern __shared__ char smraw[];
    char* tiles = (char*)((((u64)smraw) + 1023) & ~(u64)1023);
    const u32 tb0 = smem_u32(tiles);
    const int tid = threadIdx.x, lane = tid & 31, wid = tid >> 5;
    const int wm0 = (wid >> 1) * 32, wn0 = (wid & 1) * 64;   // 4M x 2N warp grid
    const int row0 = blockIdx.y * 128, col0 = blockIdx.x * 128;

    float d[2][8][4] = {};

    auto load_unit = [&](int unit, u32 tb) {
        const char *abase, *bbase; size_t astr, bstr;
        if (unit < 30) {
            abase = (const char*)(g_mext + (size_t)row0 * LDA + unit * 64); astr = LDA * 2;
            bbase = (const char*)(g_whT + (size_t)col0 * LDW + unit * 64);  bstr = LDW * 2;
        } else {
            abase = (const char*)(g_xext + ((size_t)t * BB + row0) * 64); astr = 128;
            bbase = (const char*)(g_wxext + (size_t)col0 * 64);           bstr = 128;
        }
#pragma unroll
        for (int i = 0; i < 4; i++) {
            int seg = tid + i * 256; int r = seg >> 3; int o = (seg & 7) * 16;
            cp16(tb + SWZ128(r * 128 + o), abase + (size_t)r * astr + o);
        }
#pragma unroll
        for (int i = 0; i < 4; i++) {
            int seg = tid + i * 256; int r = seg >> 3; int o = (seg & 7) * 16;
            cp16(tb + 16384 + SWZ128(r * 128 + o), bbase + (size_t)r * bstr + o);
        }
    };
    auto load_pair = [&](int c, int s) {
        load_unit(c * 2, tb0 + s * STG);
        if (c * 2 + 1 <= 30) load_unit(c * 2 + 1, tb0 + s * STG + SUB);
        asm volatile("cp.async.commit_group;" ::: "memory");
    };

    load_pair(0, 0); load_pair(1, 1);

    for (int c = 0; c < CH2P; c++) {
        int s = c & 1;
        if (c + 1 < CH2P) asm volatile("cp.async.wait_group 1;" ::: "memory");
        else              asm volatile("cp.async.wait_group 0;" ::: "memory");
        __syncthreads();
        const int nsub = (c * 2 + 1 <= 30) ? 2 : 1;
        for (int sub = 0; sub < nsub; sub++) {
            const u32 As = tb0 + s * STG + sub * SUB, Bs = As + 16384;
#pragma unroll
            for (int k16 = 0; k16 < 4; k16++) {
                u32 a[2][4], b[8][2];
#pragma unroll
                for (int mi = 0; mi < 2; mi++) {
                    int r = wm0 + mi * 16 + (lane & 15);
                    int cb = k16 * 32 + (lane >> 4) * 16;
                    u32 ad = As + r * 128 + (cb ^ ((r & 7) << 4));
                    asm volatile("ldmatrix.sync.aligned.m8n8.x4.shared.b16 {%0,%1,%2,%3}, [%4];"
                        : "=r"(a[mi][0]), "=r"(a[mi][1]), "=r"(a[mi][2]), "=r"(a[mi][3]) : "r"(ad));
                }
#pragma unroll
                for (int nb = 0; nb < 4; nb++) {
                    int l = lane & 7, q = lane >> 3;
                    int r = wn0 + nb * 16 + (q >> 1) * 8 + l;
                    int cb = k16 * 32 + (q & 1) * 16;
                    u32 ad = Bs + r * 128 + (cb ^ ((r & 7) << 4));
                    asm volatile("ldmatrix.sync.aligned.m8n8.x4.shared.b16 {%0,%1,%2,%3}, [%4];"
                        : "=r"(b[nb*2][0]), "=r"(b[nb*2][1]), "=r"(b[nb*2+1][0]), "=r"(b[nb*2+1][1]) : "r"(ad));
                }
#pragma unroll
                for (int mi = 0; mi < 2; mi++)
#pragma unroll
                    for (int ni = 0; ni < 8; ni++)
                        asm volatile("mma.sync.aligned.m16n8k16.row.col.f32.f16.f16.f32 "
                            "{%0,%1,%2,%3}, {%4,%5,%6,%7}, {%8,%9}, {%0,%1,%2,%3};"
                            : "+f"(d[mi][ni][0]), "+f"(d[mi][ni][1]),
                              "+f"(d[mi][ni][2]), "+f"(d[mi][ni][3])
                            : "r"(a[mi][0]), "r"(a[mi][1]), "r"(a[mi][2]), "r"(a[mi][3]),
                              "r"(b[ni][0]), "r"(b[ni][1]));
            }
        }
        __syncthreads();
        if (c + 2 < CH2P) load_pair(c + 2, s);
    }

    // ---- epilogue: exchange accs via smem, then full LSTM gate math ----
    __syncthreads();
    float* zt = (float*)tiles;   // [128][128] f32 = 64KB (stage region reuse)
#pragma unroll
    for (int mi = 0; mi < 2; mi++)
#pragma unroll
        for (int rh = 0; rh < 2; rh++) {
            int r = wm0 + mi * 16 + (lane >> 2) + rh * 8;
#pragma unroll
            for (int ni = 0; ni < 8; ni++) {
                int col = wn0 + ni * 8 + (lane & 3) * 2;
                *(float2*)&zt[r * 128 + col] =
                    make_float2(d[mi][ni][rh * 2], d[mi][ni][rh * 2 + 1]);
            }
        }
    __syncthreads();

    const int u = tid & 31, rgrp = tid >> 5;
    const int j = blockIdx.x * 32 + u;        // hidden unit (interleave: cols 4j+g)
    const bool jv = (j < H);
#pragma unroll
    for (int k = 0; k < 16; k++) {
        int r = rgrp * 16 + k;
        float4 q = *(float4*)&zt[r * 128 + u * 4];   // i, f, o, u
        if (jv) {
            int row = row0 + r;
            float c = g_c[row * NP1 + j];
            c = sigmf(q.y) * c + sigmf(q.x) * tanhf(q.w);
            float h = sigmf(q.z) * tanhf(c);
            g_c[row * NP1 + j] = c;
            g_hext[(size_t)row * LDA + j] = __float2half(h);
            if (row < NB) { if (g_ti[row] == t) g_toth[row * H + j] = h; }
            else { int b2 = row - NB; if (g_ei[b2] == t) g_epih[b2 * H + j] = h; }
        }
    }
}

// ---------------- classifier ----------------
__global__ void classifier_kernel(
    const float* __restrict__ bn1g, const float* __restrict__ bn1b,
    const float* __restrict__ bn1m, const float* __restrict__ bn1v,
    const float* __restrict__ W1,  const float* __restrict__ b1,
    const float* __restrict__ bn2g, const float* __restrict__ bn2b,
    const float* __restrict__ bn2m, const float* __restrict__ bn2v,
    const float* __restrict__ W2,  const float* __restrict__ b2,
    float* __restrict__ out)
{
    __shared__ float xsh[2 * H];
    __shared__ float ysh[380];
    __shared__ float red[256];
    const int b = blockIdx.x, tid = threadIdx.x;
    const int IC = 2 * H, OC = 380;
    for (int k = tid; k < IC; k += 256) {
        float v = (k < H) ? g_toth[b * H + k] : g_epih[b * H + (k - H)];
        v = (v >= 0.f) ? v : 0.3f * v;
        v = (v - bn1m[k]) / sqrtf(bn1v[k] + 1e-3f) * bn1g[k] + bn1b[k];
        xsh[k] = v;
    }
    __syncthreads();
    for (int col = tid; col < OC; col += 256) {
        float s = b1[col];
        for (int k = 0; k < IC; k++) s += xsh[k] * W1[k * OC + col];
        s = (s >= 0.f) ? s : 0.3f * s;
        s = (s - bn2m[col]) / sqrtf(bn2v[col] + 1e-3f) * bn2g[col] + bn2b[col];
        ysh[col] = s;
    }
    __syncthreads();
    float acc = 0.f;
    for (int k = tid; k < OC; k += 256) acc += ysh[k] * W2[k];
    red[tid] = acc;
    __syncthreads();
    for (int s = 128; s > 0; s >>= 1) { if (tid < s) red[tid] += red[tid + s]; __syncthreads(); }
    if (tid == 0) out[b] = red[0] + b2[0];
}

// ---------------- launch ----------------
extern "C" void kernel_launch(void* const* d_in, const int* in_sizes, int n_in,
                              void* d_out, int out_size)
{
    const int*   epi   = (const int*)  d_in[0];
    const int*   lft   = (const int*)  d_in[1];
    const int*   rgt   = (const int*)  d_in[2];
    const int*   tot   = (const int*)  d_in[3];
    const float* embed = (const float*)d_in[4];
    const float* wx    = (const float*)d_in[5];
    const float* wh    = (const float*)d_in[6];
    const float* wmx   = (const float*)d_in[7];
    const float* wmh   = (const float*)d_in[8];
    const float* bb    = (const float*)d_in[9];
    const float* gx    = (const float*)d_in[10];
    const float* gh    = (const float*)d_in[11];
    const float* gmx   = (const float*)d_in[12];
    const float* gmh   = (const float*)d_in[13];
    float* out = (float*)d_out;

    const int SM1 = 1024 + 2 * 2 * (64 + 64) * 128;   // ~66 KB (2 stages x K128 pair)
    const int SM2 = 1024 + 2 * 2 * 256 * 128;         // ~132 KB
    cudaFuncSetAttribute(gemm1, cudaFuncAttributeMaxDynamicSharedMemorySize, SM1);
    cudaFuncSetAttribute(gemm2, cudaFuncAttributeMaxDynamicSharedMemorySize, SM2);

    wnormT_kernel<<<(NP2 + 63) / 64, 64>>>(wh, gh, 0);
    wnormT_kernel<<<(NP1 + 63) / 64, 64>>>(wmh, gmh, 1);
    wmx_kernel<<<(NP1 + 127) / 128, 128>>>(wmx, gmx);
    wxext_kernel<<<(NP2 + 127) / 128, 128>>>(wx, gx, bb);
    lengths_kernel<<<1, 256>>>(epi, lft, rgt);
    embed_kernel<<<(TST * BB + 255) / 256, 256>>>(epi, tot, embed);
    init_kernel<<<(BB * NP1 + 255) / 256, 256>>>();

    for (int t = 0; t < TST; t++) {
        const int Mt = (t < TEPI) ? BB : NB;
        gemm1<<<dim3(NP1 / 64, Mt / 64), 256, SM1>>>(t);
        gemm2<<<dim3(NP2 / 128, Mt / 128), 256, SM2>>>(t);
    }

    classifier_kernel<<<NB, 256>>>(
        (const float*)d_in[14], (const float*)d_in[15], (const float*)d_in[16], (const float*)d_in[17],
        (const float*)d_in[18], (const float*)d_in[19],
        (const float*)d_in[20], (const float*)d_in[21], (const float*)d_in[22], (const float*)d_in[23],
        (const float*)d_in[24], (const float*)d_in[25], out);
}